// round 14
// baseline (speedup 1.0000x reference)
#include <cuda_runtime.h>
#include <cuda_bf16.h>
#include <cstdint>
#include <cstddef>

// out[b,c,t] = W[c, idx[b,t]] + bias[c]
//   idx: (256,1,2048) i32, W: (128,32000) f32, b: (128,) f32
//   out: (256,128,2048) f32 = 256 MB  -> store-bound.
//
// K1: W -> WT (V x 128), chunk k of row v = channels {k,k+32,k+64,k+96},
//     bias folded. 16.4 MB, L2-resident (output uses __stcs streaming).
// K2: 2048 short CTAs (8 tiles of 32 tokens each). 3-stage cp.async pipeline:
//     LDGSTS.16 gathers WT rows into XOR-swizzled token-major smem tiles
//     (no STS, no register staging); consume = 4x LDS.128 (conflict-free)
//     + in-register 4x4 transpose + 4x coalesced STG.128 streamed along t.
//     One __syncthreads per tile.

#define BB   256
#define TT   2048
#define VV   32000
#define CC   128
#define TOK  32
#define NT   8                       // tiles per CTA
#define NSTAGE 3
#define STAGE_FLOATS (TOK * CC)      // 4096 floats = 16 KB
#define SMEM_BYTES (NSTAGE * STAGE_FLOATS * 4 + NT * TOK * 4)   // 50176

__device__ float g_WT[(size_t)VV * CC];

// ---------------- K1: transpose + channel-permute + bias fold ----------------
__global__ void __launch_bounds__(256, 6)
wt_build_kernel(const float* __restrict__ W, const float* __restrict__ bias) {
    __shared__ float sm[CC][33];
    const int v0 = blockIdx.x * 32;
    const int tid = threadIdx.x;
    const int vl = tid & 31;
    const int cw = tid >> 5;

    #pragma unroll
    for (int it = 0; it < 16; ++it) {
        int c = it * 8 + cw;
        sm[c][vl] = W[(size_t)c * VV + v0 + vl];
    }
    __syncthreads();

    float4* WT4 = reinterpret_cast<float4*>(g_WT);
    #pragma unroll
    for (int it = 0; it < 4; ++it) {
        int li   = it * 256 + tid;
        int vloc = li >> 5;
        int k    = li & 31;
        float4 f;
        f.x = sm[k     ][vloc] + __ldg(&bias[k     ]);
        f.y = sm[k + 32][vloc] + __ldg(&bias[k + 32]);
        f.z = sm[k + 64][vloc] + __ldg(&bias[k + 64]);
        f.w = sm[k + 96][vloc] + __ldg(&bias[k + 96]);
        WT4[(size_t)(v0 + vloc) * 32 + k] = f;
    }
}

// Issue gather of tile i into stage s: warp w loads rows it*8+w, lane l
// copies 16B chunk l to physical chunk l ^ (row>>2) (XOR swizzle).
__device__ __forceinline__ void issue_tile(unsigned int sbase, const int* s_idx,
                                           const char* WTb, int i, int s,
                                           int w, int l) {
    unsigned int stg = sbase + (unsigned int)s * (STAGE_FLOATS * 4);
    #pragma unroll
    for (int it = 0; it < 4; ++it) {
        int j = it * 8 + w;
        const char* src = WTb + (size_t)s_idx[i * TOK + j] * 512 + l * 16;
        unsigned int dst = stg + (unsigned int)(j * 512 + ((l ^ (j >> 2)) << 4));
        asm volatile("cp.async.cg.shared.global [%0], [%1], 16;\n"
                     :: "r"(dst), "l"(src));
    }
    asm volatile("cp.async.commit_group;\n");
}

// ---------------- K2: cp.async pipelined gather + register transpose --------
__global__ void __launch_bounds__(256, 4)
gather_kernel(const int* __restrict__ idx, float* __restrict__ out) {
    extern __shared__ float sm[];                    // 3 stages of 4096 floats
    int* s_idx = (int*)(sm + NSTAGE * STAGE_FLOATS); // 256 token ids

    const int tid = threadIdx.x;
    const int w   = tid >> 5;
    const int l   = tid & 31;
    const int tau0 = blockIdx.x * NT;

    s_idx[tid] = idx[(size_t)tau0 * TOK + tid];
    __syncthreads();

    const char* WTb = (const char*)g_WT;
    const unsigned int sbase = (unsigned int)__cvta_generic_to_shared(sm);

    issue_tile(sbase, s_idx, WTb, 0, 0, w, l);
    issue_tile(sbase, s_idx, WTb, 1, 1, w, l);

    const int tg = l & 7;          // token group: tokens 4*tg .. 4*tg+3
    const int cq = l >> 3;
    const int q  = 4 * w + cq;     // logical chunk -> channels {q,q+32,q+64,q+96}
    const int pc = q ^ tg;         // physical chunk (row>>2 == tg for all 4 rows)

    #pragma unroll
    for (int i = 0; i < NT; ++i) {
        if (i < NT - 2) asm volatile("cp.async.wait_group 1;\n");
        else            asm volatile("cp.async.wait_group 0;\n");
        __syncthreads();

        const float* sb = sm + (i % NSTAGE) * STAGE_FLOATS;
        // 4 LDS.128, conflict-free: octet banks (((4w+cq)^tg)&7) all distinct
        // across the 8 tg-phases within each cq group.
        float4 v0 = *(const float4*)(sb + (4 * tg + 0) * CC + pc * 4);
        float4 v1 = *(const float4*)(sb + (4 * tg + 1) * CC + pc * 4);
        float4 v2 = *(const float4*)(sb + (4 * tg + 2) * CC + pc * 4);
        float4 v3 = *(const float4*)(sb + (4 * tg + 3) * CC + pc * 4);

        const int tau = tau0 + i;
        float* ob = out + (size_t)(tau >> 6) * CC * TT + (tau & 63) * TOK + 4 * tg;
        // In-register 4x4 transpose; 4 coalesced STG.128 (full 128B lines/warp).
        float4 o;
        o = make_float4(v0.x, v1.x, v2.x, v3.x);
        __stcs((float4*)(ob + (size_t)(q     ) * TT), o);
        o = make_float4(v0.y, v1.y, v2.y, v3.y);
        __stcs((float4*)(ob + (size_t)(q + 32) * TT), o);
        o = make_float4(v0.z, v1.z, v2.z, v3.z);
        __stcs((float4*)(ob + (size_t)(q + 64) * TT), o);
        o = make_float4(v0.w, v1.w, v2.w, v3.w);
        __stcs((float4*)(ob + (size_t)(q + 96) * TT), o);

        // Bottom-issue tile i+2 into stage (i+2)%3 == (i-1)%3: its last readers
        // (iter i-1) all passed this iteration's barrier -> race-free.
        if (i + 2 < NT)
            issue_tile(sbase, s_idx, WTb, i + 2, (i + 2) % NSTAGE, w, l);
    }
}

extern "C" void kernel_launch(void* const* d_in, const int* in_sizes, int n_in,
                              void* d_out, int out_size) {
    const int*   idx  = (const int*)  d_in[0];
    const float* W    = (const float*)d_in[1];
    const float* bias = (const float*)d_in[2];
    float*       out  = (float*)      d_out;

    cudaFuncSetAttribute(gather_kernel,
                         cudaFuncAttributeMaxDynamicSharedMemorySize, SMEM_BYTES);

    wt_build_kernel<<<VV / 32, 256>>>(W, bias);
    gather_kernel<<<(BB * TT) / (TOK * NT), 256, SMEM_BYTES>>>(idx, out);
}

// round 15
// speedup vs baseline: 1.0283x; 1.0283x over previous
#include <cuda_runtime.h>
#include <cuda_bf16.h>
#include <cstdint>
#include <cstddef>

// out[b,c,t] = W[c, idx[b,t]] + bias[c]
//   idx: (256,1,2048) i32, W: (128,32000) f32, b: (128,) f32
//   out: (256,128,2048) f32 = 256 MB  -> L2/store-bound (512MB through LTS).
//
// K1: W -> WT (V x 128), chunk k of row v = channels {k,k+32,k+64,k+96},
//     bias folded. 16.4 MB, L2-resident (output uses __stcs streaming).
// K2: 2048 CTAs x 8 tiles of 32 tokens. 2-stage cp.async pipeline at
//     6 CTAs/SM (33KB smem): LDGSTS.16 gathers WT rows into XOR-swizzled
//     token-major smem; consume = 4x LDS.128 (conflict-free) + register
//     4x4 transpose + 4x coalesced STG.128 streamed along t.
//     One __syncthreads per tile (top of iteration, after wait_group).

#define BB   256
#define TT   2048
#define VV   32000
#define CC   128
#define TOK  32
#define NT   8                       // tiles per CTA
#define NSTAGE 2
#define STAGE_FLOATS (TOK * CC)      // 4096 floats = 16 KB
#define SMEM_BYTES (NSTAGE * STAGE_FLOATS * 4 + NT * TOK * 4)   // 33792

__device__ float g_WT[(size_t)VV * CC];

// ---------------- K1: transpose + channel-permute + bias fold ----------------
__global__ void __launch_bounds__(256, 6)
wt_build_kernel(const float* __restrict__ W, const float* __restrict__ bias) {
    __shared__ float sm[CC][33];
    const int v0 = blockIdx.x * 32;
    const int tid = threadIdx.x;
    const int vl = tid & 31;
    const int cw = tid >> 5;

    #pragma unroll
    for (int it = 0; it < 16; ++it) {
        int c = it * 8 + cw;
        sm[c][vl] = W[(size_t)c * VV + v0 + vl];
    }
    __syncthreads();

    float4* WT4 = reinterpret_cast<float4*>(g_WT);
    #pragma unroll
    for (int it = 0; it < 4; ++it) {
        int li   = it * 256 + tid;
        int vloc = li >> 5;
        int k    = li & 31;
        float4 f;
        f.x = sm[k     ][vloc] + __ldg(&bias[k     ]);
        f.y = sm[k + 32][vloc] + __ldg(&bias[k + 32]);
        f.z = sm[k + 64][vloc] + __ldg(&bias[k + 64]);
        f.w = sm[k + 96][vloc] + __ldg(&bias[k + 96]);
        WT4[(size_t)(v0 + vloc) * 32 + k] = f;
    }
}

// Issue gather of tile i into stage s: warp w loads rows it*8+w, lane l
// copies 16B chunk l to physical chunk l ^ (row>>2) (XOR swizzle).
__device__ __forceinline__ void issue_tile(unsigned int sbase, const int* s_idx,
                                           const char* WTb, int i, int s,
                                           int w, int l) {
    unsigned int stg = sbase + (unsigned int)s * (STAGE_FLOATS * 4);
    #pragma unroll
    for (int it = 0; it < 4; ++it) {
        int j = it * 8 + w;
        const char* src = WTb + (size_t)s_idx[i * TOK + j] * 512 + l * 16;
        unsigned int dst = stg + (unsigned int)(j * 512 + ((l ^ (j >> 2)) << 4));
        asm volatile("cp.async.cg.shared.global [%0], [%1], 16;\n"
                     :: "r"(dst), "l"(src));
    }
    asm volatile("cp.async.commit_group;\n");
}

// ---------------- K2: cp.async pipelined gather + register transpose --------
__global__ void __launch_bounds__(256, 6)
gather_kernel(const int* __restrict__ idx, float* __restrict__ out) {
    extern __shared__ float sm[];                    // 2 stages of 4096 floats
    int* s_idx = (int*)(sm + NSTAGE * STAGE_FLOATS); // 256 token ids

    const int tid = threadIdx.x;
    const int w   = tid >> 5;
    const int l   = tid & 31;
    const int tau0 = blockIdx.x * NT;

    s_idx[tid] = idx[(size_t)tau0 * TOK + tid];
    __syncthreads();

    const char* WTb = (const char*)g_WT;
    const unsigned int sbase = (unsigned int)__cvta_generic_to_shared(sm);

    issue_tile(sbase, s_idx, WTb, 0, 0, w, l);

    const int tg = l & 7;          // token group: tokens 4*tg .. 4*tg+3
    const int cq = l >> 3;
    const int q  = 4 * w + cq;     // logical chunk -> channels {q,q+32,q+64,q+96}
    const int pc = q ^ tg;         // physical chunk (row>>2 == tg for all 4 rows)

    #pragma unroll
    for (int i = 0; i < NT; ++i) {
        asm volatile("cp.async.wait_group 0;\n");
        // Top barrier: (a) publishes all threads' cp.async data for tile i,
        // (b) all threads finished reading stage (i+1)&1 in iter i-1 -> the
        //     issue at the bottom of this iteration may overwrite it.
        __syncthreads();

        const float* sb = sm + (i & 1) * STAGE_FLOATS;
        // 4 LDS.128, conflict-free (octet banks ((q^tg)&7) distinct per phase).
        float4 v0 = *(const float4*)(sb + (4 * tg + 0) * CC + pc * 4);
        float4 v1 = *(const float4*)(sb + (4 * tg + 1) * CC + pc * 4);
        float4 v2 = *(const float4*)(sb + (4 * tg + 2) * CC + pc * 4);
        float4 v3 = *(const float4*)(sb + (4 * tg + 3) * CC + pc * 4);

        // Issue next tile ASAP (before the STG burst) to maximize overlap.
        if (i + 1 < NT)
            issue_tile(sbase, s_idx, WTb, i + 1, (i + 1) & 1, w, l);

        const int tau = tau0 + i;
        float* ob = out + (size_t)(tau >> 6) * CC * TT + (tau & 63) * TOK + 4 * tg;
        // In-register 4x4 transpose; 4 coalesced STG.128 (full 128B lines/warp).
        float4 o;
        o = make_float4(v0.x, v1.x, v2.x, v3.x);
        __stcs((float4*)(ob + (size_t)(q     ) * TT), o);
        o = make_float4(v0.y, v1.y, v2.y, v3.y);
        __stcs((float4*)(ob + (size_t)(q + 32) * TT), o);
        o = make_float4(v0.z, v1.z, v2.z, v3.z);
        __stcs((float4*)(ob + (size_t)(q + 64) * TT), o);
        o = make_float4(v0.w, v1.w, v2.w, v3.w);
        __stcs((float4*)(ob + (size_t)(q + 96) * TT), o);
    }
}

extern "C" void kernel_launch(void* const* d_in, const int* in_sizes, int n_in,
                              void* d_out, int out_size) {
    const int*   idx  = (const int*)  d_in[0];
    const float* W    = (const float*)d_in[1];
    const float* bias = (const float*)d_in[2];
    float*       out  = (float*)      d_out;

    cudaFuncSetAttribute(gather_kernel,
                         cudaFuncAttributeMaxDynamicSharedMemorySize, SMEM_BYTES);

    wt_build_kernel<<<VV / 32, 256>>>(W, bias);
    gather_kernel<<<(BB * TT) / (TOK * NT), 256, SMEM_BYTES>>>(idx, out);
}

// round 16
// speedup vs baseline: 1.0915x; 1.0614x over previous
#include <cuda_runtime.h>
#include <cuda_fp16.h>
#include <cuda_bf16.h>
#include <cstdint>
#include <cstddef>

// out[b,c,t] = W[c, idx[b,t]] + bias[c]
//   idx: (256,1,2048) i32, W: (128,32000) f32, b: (128,) f32
//   out: (256,128,2048) f32 = 256 MB.
//
// R15 evidence: 512MB through LTS = ~90% of L2 data cap; scheduling-invariant.
// => reduce bytes: WT stored as fp16 (bias folded in fp32, rounded once).
//    L2 traffic 512 -> 384 MB; DRAM stores become the binder.
//
// K1: W -> WTh (V x 128 fp16), halfs[4q..4q+3] of row v = channels
//     {q,q+32,q+64,q+96} (+bias). 8.2 MB, L2-resident.
// K2: 2048 CTAs x 8 tiles of 32 tokens, 2-stage cp.async pipeline:
//     LDGSTS.16 gathers 256B token rows into XOR-swizzled smem stages
//     (8 KB/stage); consume = 4x LDS.64 (2-phase optimal) + half2->float2
//     + register 4x4 transpose + 4x coalesced STG.128 streamed along t.

#define BB   256
#define TT   2048
#define VV   32000
#define CC   128
#define TOK  32
#define NT   8
#define NSTAGE 2
#define STAGE_BYTES (TOK * CC * 2)          // 8192
#define SMEM_BYTES (NSTAGE * STAGE_BYTES + NT * TOK * 4)   // 17408

__device__ __align__(16) __half g_WTh[(size_t)VV * CC];

union H2U { __half2 h2; unsigned u; };

// ---------------- K1: transpose + permute + bias fold + fp16 round ----------
__global__ void __launch_bounds__(256, 6)
wt_build_kernel(const float* __restrict__ W, const float* __restrict__ bias) {
    __shared__ float sm[CC][33];
    const int v0 = blockIdx.x * 32;
    const int tid = threadIdx.x;
    const int vl = tid & 31;
    const int cw = tid >> 5;

    #pragma unroll
    for (int it = 0; it < 16; ++it) {
        int c = it * 8 + cw;
        sm[c][vl] = W[(size_t)c * VV + v0 + vl];
    }
    __syncthreads();

    uint2* WTh2 = reinterpret_cast<uint2*>(g_WTh);   // 8B chunk q per row
    #pragma unroll
    for (int it = 0; it < 4; ++it) {
        int li   = it * 256 + tid;
        int vloc = li >> 5;
        int q    = li & 31;
        float4 f;
        f.x = sm[q     ][vloc] + __ldg(&bias[q     ]);
        f.y = sm[q + 32][vloc] + __ldg(&bias[q + 32]);
        f.z = sm[q + 64][vloc] + __ldg(&bias[q + 64]);
        f.w = sm[q + 96][vloc] + __ldg(&bias[q + 96]);
        H2U a, b;
        a.h2 = __floats2half2_rn(f.x, f.y);
        b.h2 = __floats2half2_rn(f.z, f.w);
        uint2 pk; pk.x = a.u; pk.y = b.u;
        WTh2[(size_t)(v0 + vloc) * 32 + q] = pk;     // 256B/warp coalesced
    }
}

// Gather tile i into stage s: 512 x 16B units; thread copies units
// it*256+tid: row j = c>>4, unit k = c&15, phys unit k ^ (j&15).
__device__ __forceinline__ void issue_tile(unsigned int sbase, const int* s_idx,
                                           const char* WTb, int i, int s,
                                           int tid) {
    unsigned int stg = sbase + (unsigned int)s * STAGE_BYTES;
    #pragma unroll
    for (int it = 0; it < 2; ++it) {
        int cidx = it * 256 + tid;
        int j = cidx >> 4;
        int k = cidx & 15;
        const char* src = WTb + (size_t)s_idx[i * TOK + j] * 256 + k * 16;
        unsigned int dst = stg + (unsigned int)(j * 256 + ((k ^ (j & 15)) << 4));
        asm volatile("cp.async.cg.shared.global [%0], [%1], 16;\n"
                     :: "r"(dst), "l"(src));
    }
    asm volatile("cp.async.commit_group;\n");
}

// ---------------- K2: fp16 gather + convert + register transpose ------------
__global__ void __launch_bounds__(256, 6)
gather_kernel(const int* __restrict__ idx, float* __restrict__ out) {
    extern __shared__ char smc[];                       // 2 stages of 8 KB
    int* s_idx = (int*)(smc + NSTAGE * STAGE_BYTES);    // 256 token ids

    const int tid = threadIdx.x;
    const int w   = tid >> 5;
    const int l   = tid & 31;
    const int tau0 = blockIdx.x * NT;

    s_idx[tid] = idx[(size_t)tau0 * TOK + tid];
    __syncthreads();

    const char* WTb = (const char*)g_WTh;
    const unsigned int sbase = (unsigned int)__cvta_generic_to_shared(smc);

    issue_tile(sbase, s_idx, WTb, 0, 0, tid);

    const int tg = l & 7;          // token group: tokens 4*tg .. 4*tg+3
    const int cq = l >> 3;
    const int q  = 4 * w + cq;     // channels {q,q+32,q+64,q+96}
    const int u  = q >> 1;         // 16B unit within row
    const int so = (q & 1) << 3;   // 8B sub-offset

    #pragma unroll
    for (int i = 0; i < NT; ++i) {
        asm volatile("cp.async.wait_group 0;\n");
        __syncthreads();   // publishes tile i; frees stage (i+1)&1 for reissue

        const char* sb = smc + (i & 1) * STAGE_BYTES;
        float4 v[4];
        #pragma unroll
        for (int m = 0; m < 4; ++m) {
            int j = 4 * tg + m;
            // phys unit = u ^ (j&15); LDS.64, 2-phase optimal (pu bijective)
            unsigned off = (unsigned)(j * 256 + ((u ^ (j & 15)) << 4) + so);
            uint2 d = *reinterpret_cast<const uint2*>(sb + off);
            H2U a, b; a.u = d.x; b.u = d.y;
            float2 f01 = __half22float2(a.h2);
            float2 f23 = __half22float2(b.h2);
            v[m] = make_float4(f01.x, f01.y, f23.x, f23.y);
        }

        if (i + 1 < NT)
            issue_tile(sbase, s_idx, WTb, i + 1, (i + 1) & 1, tid);

        const int tau = tau0 + i;
        float* ob = out + (size_t)(tau >> 6) * CC * TT + (tau & 63) * TOK + 4 * tg;
        float4 o;
        o = make_float4(v[0].x, v[1].x, v[2].x, v[3].x);
        __stcs((float4*)(ob + (size_t)(q     ) * TT), o);
        o = make_float4(v[0].y, v[1].y, v[2].y, v[3].y);
        __stcs((float4*)(ob + (size_t)(q + 32) * TT), o);
        o = make_float4(v[0].z, v[1].z, v[2].z, v[3].z);
        __stcs((float4*)(ob + (size_t)(q + 64) * TT), o);
        o = make_float4(v[0].w, v[1].w, v[2].w, v[3].w);
        __stcs((float4*)(ob + (size_t)(q + 96) * TT), o);
    }
}

extern "C" void kernel_launch(void* const* d_in, const int* in_sizes, int n_in,
                              void* d_out, int out_size) {
    const int*   idx  = (const int*)  d_in[0];
    const float* W    = (const float*)d_in[1];
    const float* bias = (const float*)d_in[2];
    float*       out  = (float*)      d_out;

    cudaFuncSetAttribute(gather_kernel,
                         cudaFuncAttributeMaxDynamicSharedMemorySize, SMEM_BYTES);

    wt_build_kernel<<<VV / 32, 256>>>(W, bias);
    gather_kernel<<<(BB * TT) / (TOK * NT), 256, SMEM_BYTES>>>(idx, out);
}